// round 1
// baseline (speedup 1.0000x reference)
#include <cuda_runtime.h>
#include <math.h>

#define NN 10000
#define EE 320000
#define FF 128
#define HH 128
#define TT 16
#define OO 128

// ---------------- static device scratch (no runtime allocation allowed) ----------------
__device__ float g_xT[TT * NN * FF];      // (T,N,F) transposed input
__device__ float g_hseq[NN * TT * HH];    // (N,T,H) top-layer states
__device__ float g_h0[NN * HH];
__device__ float g_h1[NN * HH];
__device__ float g_buf[NN * 256];         // [agg | hp or r*hp]
__device__ float g_zrbuf[NN * 256];       // z_pre | r_pre
__device__ float g_zg[NN * HH];           // sigmoid(z)
__device__ float g_tpbuf[NN * HH];        // h_tilde pre-activation
__device__ float g_ctx[NN * HH];
__device__ int   g_rowptr[NN + 1];
__device__ int   g_count[NN];
__device__ int   g_cursor[NN];
__device__ int   g_cols[EE];
__device__ float g_wraw[EE];
__device__ float g_vals[EE];
__device__ float g_dinv[NN];
__device__ float g_selfn[NN];
__device__ float g_Wzr[2 * 256 * 256];    // per layer: rows 0..127 agg-weights, 128..255 hp-weights; cols [z|r]
__device__ float g_Wh[2 * 256 * 128];
__device__ float g_bzr[2 * 256];
__device__ float g_bh[2 * 128];

struct WPtrs {
    const float* Wc[3];
    const float* bc[3];
    const float* Wl[3];
    const float* bl[3];
};

// ---------------- preprocessing kernels ----------------

__global__ void k_transpose(const float* __restrict__ x) {
    int idx = blockIdx.x * blockDim.x + threadIdx.x;   // over N*F
    if (idx >= NN * FF) return;
    const float4* xr = (const float4*)(x + (size_t)idx * TT);
    float v[16];
    float4 q;
    q = xr[0]; v[0]=q.x; v[1]=q.y; v[2]=q.z; v[3]=q.w;
    q = xr[1]; v[4]=q.x; v[5]=q.y; v[6]=q.z; v[7]=q.w;
    q = xr[2]; v[8]=q.x; v[9]=q.y; v[10]=q.z; v[11]=q.w;
    q = xr[3]; v[12]=q.x; v[13]=q.y; v[14]=q.z; v[15]=q.w;
#pragma unroll
    for (int t = 0; t < TT; t++)
        g_xT[t * (NN * FF) + idx] = v[t];
}

__global__ void k_zero() {
    int idx = blockIdx.x * blockDim.x + threadIdx.x;
    if (idx < NN * HH) { g_h0[idx] = 0.f; g_h1[idx] = 0.f; }
    if (idx < NN) g_count[idx] = 0;
}

__global__ void k_count(const int* __restrict__ ei) {
    int e = blockIdx.x * blockDim.x + threadIdx.x;
    if (e >= EE) return;
    atomicAdd(&g_count[ei[EE + e]], 1);
}

__global__ void k_scan() {
    __shared__ int sdata[1024];
    __shared__ int s_off;
    int tid = threadIdx.x;
    if (tid == 0) s_off = 0;
    __syncthreads();
    for (int base = 0; base < NN; base += 1024) {
        int v = (base + tid < NN) ? g_count[base + tid] : 0;
        sdata[tid] = v;
        __syncthreads();
        for (int d = 1; d < 1024; d <<= 1) {
            int t2 = (tid >= d) ? sdata[tid - d] : 0;
            __syncthreads();
            sdata[tid] += t2;
            __syncthreads();
        }
        int excl = sdata[tid] - v;
        if (base + tid < NN) {
            g_rowptr[base + tid] = s_off + excl;
            g_cursor[base + tid] = s_off + excl;
        }
        __syncthreads();
        int chunk_total = sdata[1023];
        if (tid == 0) s_off += chunk_total;
        __syncthreads();
    }
    if (tid == 0) g_rowptr[NN] = s_off;
}

__global__ void k_scatter(const int* __restrict__ ei, const float* __restrict__ ew) {
    int e = blockIdx.x * blockDim.x + threadIdx.x;
    if (e >= EE) return;
    int d = ei[EE + e];
    int p = atomicAdd(&g_cursor[d], 1);
    g_cols[p] = ei[e];
    g_wraw[p] = ew[e];
}

__global__ void k_deg() {
    int row = blockIdx.x * blockDim.y + threadIdx.y;
    int lane = threadIdx.x;
    if (row >= NN) return;
    int p0 = g_rowptr[row], p1 = g_rowptr[row + 1];
    float s = 0.f;
    for (int p = p0 + lane; p < p1; p += 32) s += g_wraw[p];
#pragma unroll
    for (int o = 16; o > 0; o >>= 1) s += __shfl_xor_sync(0xffffffffu, s, o);
    if (lane == 0) {
        float dinv = rsqrtf(s + 1.0f);
        g_dinv[row] = dinv;
        g_selfn[row] = dinv * dinv;
    }
}

__global__ void k_normvals() {
    int row = blockIdx.x * blockDim.y + threadIdx.y;
    int lane = threadIdx.x;
    if (row >= NN) return;
    int p0 = g_rowptr[row], p1 = g_rowptr[row + 1];
    float dv = g_dinv[row];
    for (int p = p0 + lane; p < p1; p += 32)
        g_vals[p] = dv * g_wraw[p] * g_dinv[g_cols[p]];
}

// Fused weights: W1 = Wc @ Wl_top, bottom rows copied, bias = bc @ Wl_top + bl.
__global__ void k_prep(WPtrs P) {
    int lg = blockIdx.y;                // 0..5
    int l = lg / 3, g = lg % 3;
    int i = blockIdx.x;                 // row 0..127
    int j = threadIdx.x;                // col 0..127
    const float* Wc = P.Wc[g] + l * HH * HH;
    const float* Wl = P.Wl[g] + l * 2 * HH * HH;
    float c = 0.f;
    for (int k = 0; k < HH; k++) c += Wc[i * HH + k] * Wl[k * HH + j];
    float bot = Wl[(HH + i) * HH + j];
    if (g < 2) {
        g_Wzr[l * 256 * 256 + i * 256 + g * HH + j] = c;
        g_Wzr[l * 256 * 256 + (HH + i) * 256 + g * HH + j] = bot;
    } else {
        g_Wh[l * 256 * 128 + i * 128 + j] = c;
        g_Wh[l * 256 * 128 + (HH + i) * 128 + j] = bot;
    }
    if (i == 0) {
        const float* bc = P.bc[g] + l * HH;
        const float* bl = P.bl[g] + l * HH;
        float b = 0.f;
        for (int k = 0; k < HH; k++) b += bc[k] * Wl[k * HH + j];
        b += bl[j];
        if (g < 2) g_bzr[l * 256 + g * HH + j] = b;
        else       g_bh[l * 128 + j] = b;
    }
}

// ---------------- main-loop kernels ----------------

// out (N x 256 row-major): cols 0..127 = A_norm @ in (incl. self-loop term), cols 128..255 = copy of hp.
__global__ void k_spmm(const float* __restrict__ in, const float* __restrict__ hp,
                       float* __restrict__ out) {
    int row = blockIdx.x * blockDim.y + threadIdx.y;
    if (row >= NN) return;
    int lane = threadIdx.x;
    const float4* in4 = (const float4*)in;
    float sn = g_selfn[row];
    float4 hv = in4[row * 32 + lane];
    float ax = sn * hv.x, ay = sn * hv.y, az = sn * hv.z, aw = sn * hv.w;
    float bx = 0.f, by = 0.f, bz = 0.f, bw = 0.f;
    int p = g_rowptr[row], pe = g_rowptr[row + 1];
    for (; p + 1 < pe; p += 2) {
        float v0 = g_vals[p],     v1 = g_vals[p + 1];
        int   c0 = g_cols[p],     c1 = g_cols[p + 1];
        float4 b0 = in4[c0 * 32 + lane];
        float4 b1 = in4[c1 * 32 + lane];
        ax += v0 * b0.x; ay += v0 * b0.y; az += v0 * b0.z; aw += v0 * b0.w;
        bx += v1 * b1.x; by += v1 * b1.y; bz += v1 * b1.z; bw += v1 * b1.w;
    }
    if (p < pe) {
        float v0 = g_vals[p]; int c0 = g_cols[p];
        float4 b0 = in4[c0 * 32 + lane];
        ax += v0 * b0.x; ay += v0 * b0.y; az += v0 * b0.z; aw += v0 * b0.w;
    }
    float4 acc = make_float4(ax + bx, ay + by, az + bz, aw + bw);
    float4* out4 = (float4*)out;
    out4[row * 64 + lane] = acc;
    out4[row * 64 + 32 + lane] = ((const float4*)hp)[row * 32 + lane];
}

// C[M x Nc] = A[M x K] @ B[K x Nc] + bias ; BM=128, BN=64, BK=16, 256 threads, 8x4 per thread.
__global__ void __launch_bounds__(256)
k_gemm(const float* __restrict__ A, const float* __restrict__ B,
       const float* __restrict__ bias, float* __restrict__ C,
       int M, int K, int Nc) {
    __shared__ float As[16][128];
    __shared__ float Bs[16][64];
    int tid = threadIdx.x;
    int tx = tid & 15, ty = tid >> 4;
    int row0 = blockIdx.x * 128;
    int col0 = blockIdx.y * 64;
    float acc[8][4];
#pragma unroll
    for (int i = 0; i < 8; i++)
#pragma unroll
        for (int j = 0; j < 4; j++) acc[i][j] = 0.f;

    for (int kt = 0; kt < K; kt += 16) {
#pragma unroll
        for (int i = 0; i < 2; i++) {
            int lid = tid + i * 256;
            int m = lid >> 2, kq = lid & 3;
            int grow = row0 + m;
            float4 a = (grow < M) ? *(const float4*)&A[grow * K + kt + kq * 4]
                                  : make_float4(0.f, 0.f, 0.f, 0.f);
            As[kq * 4 + 0][m] = a.x;
            As[kq * 4 + 1][m] = a.y;
            As[kq * 4 + 2][m] = a.z;
            As[kq * 4 + 3][m] = a.w;
        }
        {
            int kb = tid >> 4, nq = tid & 15;
            float4 b = *(const float4*)&B[(kt + kb) * Nc + col0 + nq * 4];
            *(float4*)&Bs[kb][nq * 4] = b;
        }
        __syncthreads();
#pragma unroll
        for (int k = 0; k < 16; k++) {
            float a[8], bf[4];
            *(float4*)&a[0] = *(const float4*)&As[k][ty * 8];
            *(float4*)&a[4] = *(const float4*)&As[k][ty * 8 + 4];
            *(float4*)&bf[0] = *(const float4*)&Bs[k][tx * 4];
#pragma unroll
            for (int i = 0; i < 8; i++)
#pragma unroll
                for (int j = 0; j < 4; j++) acc[i][j] += a[i] * bf[j];
        }
        __syncthreads();
    }
#pragma unroll
    for (int i = 0; i < 8; i++) {
        int grow = row0 + ty * 8 + i;
        if (grow < M) {
#pragma unroll
            for (int j = 0; j < 4; j++) {
                int gc = col0 + tx * 4 + j;
                C[grow * Nc + gc] = acc[i][j] + bias[gc];
            }
        }
    }
}

// z = sigmoid(z_pre), r = sigmoid(r_pre); store z; overwrite buf cols 128..255 with r*hp.
__global__ void k_pw1(const float* __restrict__ hp) {
    int idx = blockIdx.x * blockDim.x + threadIdx.x;
    if (idx >= NN * HH) return;
    int n = idx >> 7, h = idx & 127;
    float z = 1.f / (1.f + expf(-g_zrbuf[n * 256 + h]));
    float r = 1.f / (1.f + expf(-g_zrbuf[n * 256 + 128 + h]));
    float hv = hp[idx];
    g_zg[idx] = z;
    g_buf[n * 256 + 128 + h] = r * hv;
}

// h_new = z*hp + (1-z)*tanh(t_pre); update state, optionally record top-layer sequence.
__global__ void k_pw2(float* __restrict__ hstate, int t, int wseq) {
    int idx = blockIdx.x * blockDim.x + threadIdx.x;
    if (idx >= NN * HH) return;
    int n = idx >> 7, h = idx & 127;
    float ht = tanhf(g_tpbuf[idx]);
    float z = g_zg[idx];
    float hv = hstate[idx];
    float hn = z * hv + (1.f - z) * ht;
    hstate[idx] = hn;
    if (wseq) g_hseq[n * (TT * HH) + t * HH + h] = hn;
}

// Temporal attention: warp per node. att_b cancels inside softmax (constant shift).
__global__ void __launch_bounds__(128)
k_attn(const float* __restrict__ attW) {
    int n = blockIdx.x * blockDim.y + threadIdx.y;
    if (n >= NN) return;
    int lane = threadIdx.x;
    float4 aw = ((const float4*)attW)[lane];
    const float4* h4 = (const float4*)g_hseq + n * (TT * HH / 4) + lane;
    float4 hv[16];
    float s[16];
#pragma unroll
    for (int t = 0; t < TT; t++) {
        hv[t] = h4[t * 32];
        float d = hv[t].x * aw.x + hv[t].y * aw.y + hv[t].z * aw.z + hv[t].w * aw.w;
#pragma unroll
        for (int o = 16; o > 0; o >>= 1) d += __shfl_xor_sync(0xffffffffu, d, o);
        s[t] = d;
    }
    float m = s[0];
#pragma unroll
    for (int t = 1; t < TT; t++) m = fmaxf(m, s[t]);
    float sum = 0.f;
#pragma unroll
    for (int t = 0; t < TT; t++) { s[t] = expf(s[t] - m); sum += s[t]; }
    float inv = 1.f / sum;
    float4 c = make_float4(0.f, 0.f, 0.f, 0.f);
#pragma unroll
    for (int t = 0; t < TT; t++) {
        float w = s[t] * inv;
        c.x += w * hv[t].x; c.y += w * hv[t].y; c.z += w * hv[t].z; c.w += w * hv[t].w;
    }
    ((float4*)g_ctx)[n * 32 + lane] = c;
}

// ---------------- launch ----------------

extern "C" void kernel_launch(void* const* d_in, const int* in_sizes, int n_in,
                              void* d_out, int out_size) {
    const float* x   = (const float*)d_in[0];
    const int*   ei  = (const int*)d_in[1];
    const float* ew  = (const float*)d_in[2];
    WPtrs P;
    P.Wc[0] = (const float*)d_in[3];  P.bc[0] = (const float*)d_in[4];
    P.Wl[0] = (const float*)d_in[5];  P.bl[0] = (const float*)d_in[6];
    P.Wc[1] = (const float*)d_in[7];  P.bc[1] = (const float*)d_in[8];
    P.Wl[1] = (const float*)d_in[9];  P.bl[1] = (const float*)d_in[10];
    P.Wc[2] = (const float*)d_in[11]; P.bc[2] = (const float*)d_in[12];
    P.Wl[2] = (const float*)d_in[13]; P.bl[2] = (const float*)d_in[14];
    const float* attW = (const float*)d_in[15];
    const float* outW = (const float*)d_in[17];
    const float* outb = (const float*)d_in[18];
    float* out = (float*)d_out;

    float *p_xT, *p_h0, *p_h1, *p_buf, *p_zr, *p_tp, *p_ctx, *p_Wzr, *p_Wh, *p_bzr, *p_bh;
    cudaGetSymbolAddress((void**)&p_xT,  g_xT);
    cudaGetSymbolAddress((void**)&p_h0,  g_h0);
    cudaGetSymbolAddress((void**)&p_h1,  g_h1);
    cudaGetSymbolAddress((void**)&p_buf, g_buf);
    cudaGetSymbolAddress((void**)&p_zr,  g_zrbuf);
    cudaGetSymbolAddress((void**)&p_tp,  g_tpbuf);
    cudaGetSymbolAddress((void**)&p_ctx, g_ctx);
    cudaGetSymbolAddress((void**)&p_Wzr, g_Wzr);
    cudaGetSymbolAddress((void**)&p_Wh,  g_Wh);
    cudaGetSymbolAddress((void**)&p_bzr, g_bzr);
    cudaGetSymbolAddress((void**)&p_bh,  g_bh);

    const int PWB = (NN * HH + 255) / 256;          // 5000
    const int GX = (NN + 127) / 128;                // 79

    k_transpose<<<(NN * FF + 255) / 256, 256>>>(x);
    k_zero<<<PWB, 256>>>();
    k_count<<<(EE + 255) / 256, 256>>>(ei);
    k_scan<<<1, 1024>>>();
    k_scatter<<<(EE + 255) / 256, 256>>>(ei, ew);
    k_deg<<<(NN + 7) / 8, dim3(32, 8)>>>();
    k_normvals<<<(NN + 7) / 8, dim3(32, 8)>>>();
    k_prep<<<dim3(HH, 6), HH>>>(P);

    for (int t = 0; t < TT; t++) {
        // ---- layer 0 (input = x_t) ----
        k_spmm<<<(NN + 7) / 8, dim3(32, 8)>>>(p_xT + (size_t)t * NN * FF, p_h0, p_buf);
        k_gemm<<<dim3(GX, 4), 256>>>(p_buf, p_Wzr, p_bzr, p_zr, NN, 256, 256);
        k_pw1<<<PWB, 256>>>(p_h0);
        k_gemm<<<dim3(GX, 2), 256>>>(p_buf, p_Wh, p_bh, p_tp, NN, 256, 128);
        k_pw2<<<PWB, 256>>>(p_h0, t, 0);
        // ---- layer 1 (input = new h0) ----
        k_spmm<<<(NN + 7) / 8, dim3(32, 8)>>>(p_h0, p_h1, p_buf);
        k_gemm<<<dim3(GX, 4), 256>>>(p_buf, p_Wzr + 256 * 256, p_bzr + 256, p_zr, NN, 256, 256);
        k_pw1<<<PWB, 256>>>(p_h1);
        k_gemm<<<dim3(GX, 2), 256>>>(p_buf, p_Wh + 256 * 128, p_bh + 128, p_tp, NN, 256, 128);
        k_pw2<<<PWB, 256>>>(p_h1, t, 1);
    }

    k_attn<<<(NN + 3) / 4, dim3(32, 4)>>>(attW);
    k_gemm<<<dim3(GX, 2), 256>>>(p_ctx, outW, outb, out, NN, 128, 128);
}